// round 8
// baseline (speedup 1.0000x reference)
#include <cuda_runtime.h>
#include <cstdint>

#define BB    256
#define LL    512
#define DD    64
#define NID   10000
#define TROWS 8      // table rows; counts >= 8 take the (never-hit) uniform cold path

// ---------------------------------------------------------------------------
// One CTA per batch. Packed smem histogram (lo16 = count of id in src seq,
// hi16 = count in dst seq). 8x64 g-table built concurrently with the atomics.
// Branch-free interleaved store loop: per iteration one src row + one dst row,
// 1 LDS.64 (packed counts) + 4 LDS.128 (table) + 2 STG.128.
// ---------------------------------------------------------------------------
__global__ void __launch_bounds__(512) fused_encode(
        const int* __restrict__ src,
        const int* __restrict__ dst,
        const float* __restrict__ W1,
        const float* __restrict__ b1,
        const float* __restrict__ W2,
        const float* __restrict__ b2,
        float* __restrict__ out) {
    __shared__ __align__(16) uint32_t hist[NID];          // 40000 B
    __shared__ __align__(16) float    table[TROWS * DD];  //  2048 B
    __shared__ __align__(16) uint2    csd[LL];            //  4096 B
    __shared__ float w1s[DD], b1s[DD], b2s[DD];           //   768 B
    __shared__ uint32_t maxc;

    const int t = threadIdx.x;
    const int b = blockIdx.x;

    // ---- P0: zero histogram (128-bit), stage params, load ids ----
    const uint4 z = make_uint4(0u, 0u, 0u, 0u);
    #pragma unroll
    for (int i = t; i < NID / 4; i += 512) ((uint4*)hist)[i] = z;
    if (t < DD)            w1s[t]          = W1[t];
    else if (t < 2 * DD)   b1s[t - DD]     = b1[t - DD];
    else if (t < 3 * DD)   b2s[t - 2 * DD] = b2[t - 2 * DD];
    if (t == 0) maxc = 0u;

    const int sid = src[b * LL + t];
    const int did = dst[b * LL + t];
    __syncthreads();

    // ---- P1: packed dual histogram + (concurrently) 8x64 table build ----
    atomicAdd(&hist[sid], 1u);
    atomicAdd(&hist[did], 0x10000u);
    {
        const int a = t >> 6, e = t & 63;       // 512 threads = 8 rows x 64 cols
        const float fa = (float)a;
        float s = b2s[e];
        const float4* w2r4 = (const float4*)(W2 + e * DD);
        #pragma unroll 4
        for (int j = 0; j < 16; ++j) {
            const float4 w4 = __ldg(&w2r4[j]);
            const int d = j * 4;
            const float h0 = fmaxf(fmaf(fa, w1s[d + 0], b1s[d + 0]), 0.f);
            const float h1 = fmaxf(fmaf(fa, w1s[d + 1], b1s[d + 1]), 0.f);
            const float h2 = fmaxf(fmaf(fa, w1s[d + 2], b1s[d + 2]), 0.f);
            const float h3 = fmaxf(fmaf(fa, w1s[d + 3], b1s[d + 3]), 0.f);
            s = fmaf(h0, w4.x, s);
            s = fmaf(h1, w4.y, s);
            s = fmaf(h2, w4.z, s);
            s = fmaf(h3, w4.w, s);
        }
        table[t] = s;
    }
    __syncthreads();

    // ---- P2: packed per-position counts (id 0 = padding -> (0,0)); max ----
    const uint32_t hs = sid ? hist[sid] : 0u;
    const uint32_t hd = did ? hist[did] : 0u;
    csd[t] = make_uint2(hs, hd);
    uint32_t m = max(max(hs & 0xFFFFu, hs >> 16), max(hd & 0xFFFFu, hd >> 16));
    m = __reduce_max_sync(0xFFFFFFFFu, m);
    if ((t & 31) == 0) atomicMax(&maxc, m);
    __syncthreads();

    // ---- P3: store 512 KB, interleaved src/dst, branch-free hot loop ----
    const int lane = t & 15;
    float4* __restrict__ osrc = (float4*)(out + (size_t)b * LL * DD);
    float4* __restrict__ odst = (float4*)(out + ((size_t)BB + b) * LL * DD);

    if (maxc < TROWS) {
        const float4* __restrict__ T4 = (const float4*)table;
        #pragma unroll 2
        for (int r = (t >> 4); r < LL; r += 32) {
            const uint2 c = csd[r];
            const float4 s0 = T4[(c.x & 0xFFFFu) * 16 + lane];
            const float4 s1 = T4[(c.x >> 16)     * 16 + lane];
            const float4 d0 = T4[(c.y & 0xFFFFu) * 16 + lane];
            const float4 d1 = T4[(c.y >> 16)     * 16 + lane];
            float4 ws, wd;
            ws.x = s0.x + s1.x; ws.y = s0.y + s1.y;
            ws.z = s0.z + s1.z; ws.w = s0.w + s1.w;
            wd.x = d0.x + d1.x; wd.y = d0.y + d1.y;
            wd.z = d0.z + d1.z; wd.w = d0.w + d1.w;
            osrc[r * 16 + lane] = ws;
            odst[r * 16 + lane] = wd;
        }
    } else {
        // CTA-uniform cold path (never taken with this data): direct compute.
        for (int r = (t >> 4); r < LL; r += 32) {
            const uint2 c = csd[r];
            float4 accs, accd;
            accs.x = 2.f * b2s[lane * 4 + 0]; accd.x = accs.x;
            accs.y = 2.f * b2s[lane * 4 + 1]; accd.y = accs.y;
            accs.z = 2.f * b2s[lane * 4 + 2]; accd.z = accs.z;
            accs.w = 2.f * b2s[lane * 4 + 3]; accd.w = accs.w;
            const float sa0 = (float)(c.x & 0xFFFFu), sa1 = (float)(c.x >> 16);
            const float da0 = (float)(c.y & 0xFFFFu), da1 = (float)(c.y >> 16);
            for (int d = 0; d < DD; ++d) {
                const float hsum_s = fmaxf(fmaf(sa0, w1s[d], b1s[d]), 0.f)
                                   + fmaxf(fmaf(sa1, w1s[d], b1s[d]), 0.f);
                const float hsum_d = fmaxf(fmaf(da0, w1s[d], b1s[d]), 0.f)
                                   + fmaxf(fmaf(da1, w1s[d], b1s[d]), 0.f);
                accs.x = fmaf(hsum_s, __ldg(&W2[(lane*4+0)*DD + d]), accs.x);
                accs.y = fmaf(hsum_s, __ldg(&W2[(lane*4+1)*DD + d]), accs.y);
                accs.z = fmaf(hsum_s, __ldg(&W2[(lane*4+2)*DD + d]), accs.z);
                accs.w = fmaf(hsum_s, __ldg(&W2[(lane*4+3)*DD + d]), accs.w);
                accd.x = fmaf(hsum_d, __ldg(&W2[(lane*4+0)*DD + d]), accd.x);
                accd.y = fmaf(hsum_d, __ldg(&W2[(lane*4+1)*DD + d]), accd.y);
                accd.z = fmaf(hsum_d, __ldg(&W2[(lane*4+2)*DD + d]), accd.z);
                accd.w = fmaf(hsum_d, __ldg(&W2[(lane*4+3)*DD + d]), accd.w);
            }
            osrc[r * 16 + lane] = accs;
            odst[r * 16 + lane] = accd;
        }
    }
}

// ---------------------------------------------------------------------------
// Inputs: 0 src_ids, 1 dst_ids, 2 W1(D,1), 3 b1(D), 4 W2(D,D), 5 b2(D)
// Output: [src_feat | dst_feat], each B*L*D f32.
// ---------------------------------------------------------------------------
extern "C" void kernel_launch(void* const* d_in, const int* in_sizes, int n_in,
                              void* d_out, int out_size) {
    const int*   src = (const int*)d_in[0];
    const int*   dst = (const int*)d_in[1];
    const float* W1  = (const float*)d_in[2];
    const float* b1  = (const float*)d_in[3];
    const float* W2  = (const float*)d_in[4];
    const float* b2  = (const float*)d_in[5];
    float* out = (float*)d_out;

    fused_encode<<<BB, 512>>>(src, dst, W1, b1, W2, b2, out);
}